// round 15
// baseline (speedup 1.0000x reference)
#include <cuda_runtime.h>
#include <math.h>

#define NF     40
#define NG     4
#define GF     10
#define TT     64000
#define NBATCH 32
#define NP     400
#define WSMAX  404
#define POSB   512          // positions per pass-1 block (256 threads x 2)
#define WGTCAP 8192         // per-group weight floats (cs*qm*20 + 12)
#define CONV_SMEM 43008
#define POOL_SMEM 46080
#define PT     64           // pool outputs per block
#define PSUB   8            // w-segments per output
// pool smem float offsets
#define ES_OFF   0
#define WIN_OFF  10496      // es span max = 63*160+401 = 10481
#define PART_OFF 10912      // wins <= 401
// total floats = 10912 + 512 = 11424 -> 45696 B

// ---- per-launch-computed meta + tables + scratch (zero-init .bss) ----
__device__ int   d_cs[NG], d_ps[NG], d_k[NG], d_qn[NG], d_qm[NG], d_ws[NG], d_L[NG];
__device__ int   d_ebase[NG];
__device__ float d_wgt[NG][WGTCAP];           // [r][q][f*2+{cos,sin}] pairs + center norms
__device__ float d_win[NG][GF][WSMAX];
__device__ float d_energy[81920000];          // [g]{[f][b][j]} planes

// ============================================================================
// Setup 1: meta. One tiny block.
// ============================================================================
__global__ void setup_meta(const float* __restrict__ cf,
                           const float* __restrict__ bw) {
    const int tid = threadIdx.x;
    const double Zd  = sqrt(2.0 * log(2.0)) / M_PI;
    const float bwlo = (float)(2.0   * Zd);
    const float bwhi = (float)(401.0 * Zd);
    const float pi_f = (float)M_PI;

    if (tid < NG) {
        const int g = tid;
        float cfm = 0.f, bwm = 0.f;
        for (int f = 0; f < GF; f++) {
            float c = fminf(fmaxf(cf[g * GF + f], 0.f), pi_f);
            float b = fminf(fmaxf(bw[g * GF + f], bwlo), bwhi);
            cfm = fmaxf(cfm, c);
            bwm = fmaxf(bwm, b);
        }
        double s = M_PI / (double)cfm;
        if (s < 1.0) s = 1.0;
        const int divs[12] = {160, 80, 40, 32, 20, 16, 10, 8, 5, 4, 2, 1};
        int cs = 1;
        for (int i = 0; i < 12; i++)
            if ((double)divs[i] <= s) { cs = divs[i]; break; }
        int k = (int)((double)bwm * 3.0);
        if ((k & 1) == 0) k += 1;
        int ws = (int)(401.0 / (double)cs + 0.5);
        if ((ws & 1) == 0) ws += 1;

        const int kh = k >> 1;
        d_cs[g] = cs;
        d_ps[g] = 160 / cs;
        d_k[g]  = k;
        d_qn[g] = (k + cs - 1) / cs;
        d_qm[g] = kh / cs + 1;        // pair-slot count per residue
        d_ws[g] = ws;
        d_L[g]  = (TT - 1) / cs + 1;
    }
    __syncthreads();
    if (tid == 0) {
        int acc = 0;
        for (int g = 0; g < NG; g++) {
            d_ebase[g] = acc;
            acc += NBATCH * d_L[g] * GF;
        }
    }
}

// ============================================================================
// Setup 2: symmetric-pair Gabor weights + pooling windows. grid (8, NG) x 256.
// Pair (r, q) -> tap t = q*cs + r (t in [1, kh]); slot holds
// [f*2+0] = norm*cos(t*cf)*gauss(t)  (applied to x+ + x-)
// [f*2+1] = norm*sin(t*cf)*gauss(t)  (applied to x+ - x-)
// Center norms (t=0) appended at offset cs*qm*20 (10 floats, 2 pad zeros).
// ============================================================================
__global__ void setup_weights(const float* __restrict__ cf,
                              const float* __restrict__ bw,
                              const float* __restrict__ pw) {
    const int g   = blockIdx.y;
    const int cs  = d_cs[g];
    const int qmA = d_qm[g];
    const int k   = d_k[g];
    const int ws  = d_ws[g];
    const int kh  = k >> 1;

    const double Zd  = sqrt(2.0 * log(2.0)) / M_PI;
    const float bwlo = (float)(2.0   * Zd);
    const float bwhi = (float)(401.0 * Zd);
    const float pi_f = (float)M_PI;

    const int stride = gridDim.x * blockDim.x;
    const int t0 = blockIdx.x * blockDim.x + threadIdx.x;

    const int wtot = cs * qmA * 20;
    for (int i = t0; i < wtot; i += stride) {
        const int qr  = i / 20;
        const int f2  = i - qr * 20;
        const int f   = f2 >> 1;
        const int sel = f2 & 1;
        const int r   = qr / qmA;
        const int q   = qr - r * qmA;
        const int t   = q * cs + r;
        float v = 0.f;
        if (t >= 1 && t <= kh) {
            const int gi = g * GF + f;
            const float cfc = fminf(fmaxf(cf[gi], 0.f), pi_f);
            const float bwc = fminf(fmaxf(bw[gi], bwlo), bwhi);
            const double td = (double)t;
            const double bd = (double)bwc;
            const double gauss = exp(-(td * td) / (2.0 * bd * bd));
            const double norm  = 1.0 / (sqrt(2.0 * M_PI) * bd);
            double sn, csn;
            sincos(td * (double)cfc, &sn, &csn);
            v = (float)(norm * (sel ? sn : csn) * gauss);
        }
        d_wgt[g][i] = v;
    }
    // center norms
    for (int i = t0; i < GF; i += stride) {
        const int gi = g * GF + i;
        const float bwc = fminf(fmaxf(bw[gi], bwlo), bwhi);
        d_wgt[g][wtot + i] = (float)(1.0 / (sqrt(2.0 * M_PI) * (double)bwc));
    }
    if (t0 < 2) d_wgt[g][wtot + GF + t0] = 0.f;   // pad for float4 reads

    // pooling windows
    for (int i = t0; i < GF * ws; i += stride) {
        const int f = i / ws;
        const int w = i - f * ws;
        const int gi = g * GF + f;
        const float pwc = fminf(fmaxf(pw[gi], (float)(2.0 / 401.0)), 0.5f);
        const double sigma = (double)pwc / (double)cs * 401.0 / (double)ws;
        const double c = 0.5 * (double)(ws - 1);
        const double u = ((double)w - c) / (sigma * c);
        d_win[g][f][w] = (float)exp(-0.5 * u * u);
    }
}

// ============================================================================
// Pass 1: symmetric Gabor conv energy (scalar FFMA — measured fastest).
// 256 threads = 512 positions, all 10 filters per thread. Even/odd symmetry:
// per tap-pair shared u = x+ + x-, d = x+ - x- feed 20 FMAs per position pair.
// ============================================================================
__global__ __launch_bounds__(256) void conv_kernel(const float* __restrict__ x) {
    const int g = blockIdx.z;
    const int b = blockIdx.y;

    const int cs  = d_cs[g];
    const int qn  = d_qn[g];
    const int qmA = d_qm[g];
    const int L   = d_L[g];
    const int kh  = d_k[g] >> 1;

    const int j0 = blockIdx.x * POSB;
    if (j0 >= L) return;

    const int mlen  = POSB / 2 + 256 + qn;
    const int mlenP = mlen | 1;

    extern __shared__ float sm[];
    float* xr = sm;                                     // [cs][mlenP]
    const int wofs = ((cs * mlenP) + 3) & ~3;
    float* wsm = sm + wofs;                             // pairs + center

    const int tid  = threadIdx.x;
    const int gofs = j0 * cs - kh;
    const float* xb = x + b * TT;

    const int xtot = cs * mlen;
    for (int i = tid; i < xtot; i += 256) {
        const int gi = gofs + i;
        const float v = ((unsigned)gi < (unsigned)TT) ? xb[gi] : 0.f;
        const int r = i % cs;
        const int m = i / cs;
        xr[r * mlenP + m] = v;
    }
    const int wtot = cs * qmA * 20 + 12;
    for (int i = tid; i < wtot; i += 256)
        wsm[i] = d_wgt[g][i];
    __syncthreads();

    float C0[GF], S0[GF], C1[GF], S1[GF];
    #pragma unroll
    for (int f = 0; f < GF; f++) { C0[f] = S0[f] = C1[f] = S1[f] = 0.f; }

    // Center tap (t = 0): contributes only to C (sin(0)=0).
    {
        const float* rowC = xr + (kh % cs) * mlenP + (kh / cs) + tid;
        const float xc0 = rowC[0];
        const float xc1 = rowC[256];
        const float4* c4 = reinterpret_cast<const float4*>(wsm + cs * qmA * 20);
        const float4 n0 = c4[0], n1 = c4[1], n2 = c4[2];
        C0[0] = fmaf(n0.x, xc0, C0[0]); C1[0] = fmaf(n0.x, xc1, C1[0]);
        C0[1] = fmaf(n0.y, xc0, C0[1]); C1[1] = fmaf(n0.y, xc1, C1[1]);
        C0[2] = fmaf(n0.z, xc0, C0[2]); C1[2] = fmaf(n0.z, xc1, C1[2]);
        C0[3] = fmaf(n0.w, xc0, C0[3]); C1[3] = fmaf(n0.w, xc1, C1[3]);
        C0[4] = fmaf(n1.x, xc0, C0[4]); C1[4] = fmaf(n1.x, xc1, C1[4]);
        C0[5] = fmaf(n1.y, xc0, C0[5]); C1[5] = fmaf(n1.y, xc1, C1[5]);
        C0[6] = fmaf(n1.z, xc0, C0[6]); C1[6] = fmaf(n1.z, xc1, C1[6]);
        C0[7] = fmaf(n1.w, xc0, C0[7]); C1[7] = fmaf(n1.w, xc1, C1[7]);
        C0[8] = fmaf(n2.x, xc0, C0[8]); C1[8] = fmaf(n2.x, xc1, C1[8]);
        C0[9] = fmaf(n2.y, xc0, C0[9]); C1[9] = fmaf(n2.y, xc1, C1[9]);
    }

    // Tap pairs t = q*cs + r, t in [1, kh].
    #pragma unroll 1
    for (int r = 0; r < cs; r++) {
        const int qlo = (r == 0) ? 1 : 0;
        const int aM  = (kh - r) / cs;
        const int sM  = (kh - r) % cs;
        const int bP  = (kh + r) / cs;
        const int sP  = (kh + r) % cs;
        const float* rowP = xr + sP * mlenP + tid + bP;
        const float* rowM = xr + sM * mlenP + tid + aM;
        const float* wr = wsm + r * qmA * 20;
        #pragma unroll 1
        for (int q = qlo; q <= aM; q++) {
            const float xp0 = rowP[q];
            const float xm0 = rowM[-q];
            const float xp1 = rowP[256 + q];
            const float xm1 = rowM[256 - q];
            const float u0 = xp0 + xm0, dd0 = xp0 - xm0;
            const float u1 = xp1 + xm1, dd1 = xp1 - xm1;
            const float4* w4 = reinterpret_cast<const float4*>(wr + q * 20);
            #pragma unroll
            for (int c = 0; c < 5; c++) {
                const float4 w = w4[c];
                const int f0 = 2 * c, f1 = 2 * c + 1;
                C0[f0] = fmaf(w.x, u0,  C0[f0]);
                S0[f0] = fmaf(w.y, dd0, S0[f0]);
                C0[f1] = fmaf(w.z, u0,  C0[f1]);
                S0[f1] = fmaf(w.w, dd0, S0[f1]);
                C1[f0] = fmaf(w.x, u1,  C1[f0]);
                S1[f0] = fmaf(w.y, dd1, S1[f0]);
                C1[f1] = fmaf(w.z, u1,  C1[f1]);
                S1[f1] = fmaf(w.w, dd1, S1[f1]);
            }
        }
    }

    // Plane stores: e[f][b][j] — coalesced per filter.
    float* eg = d_energy + d_ebase[g];
    const int ja = j0 + tid;
    const int jb = j0 + 256 + tid;
    #pragma unroll
    for (int f = 0; f < GF; f++) {
        float* pf = eg + (f * NBATCH + b) * L;
        if (ja < L) pf[ja] = fmaf(C0[f], C0[f], S0[f] * S0[f]);
        if (jb < L) pf[jb] = fmaf(C1[f], C1[f], S1[f] * S1[f]);
    }
}

// ============================================================================
// Pass 2: pooling, thread-per-output from smem-staged energy.
// Block = (p-tile of 64, b, g*f). 512 threads = 64 outputs x 8 w-segments.
// Skewed start offset avoids bank conflicts; inner loop split into TWO LINEAR
// segments (no per-iteration wrap check) and unrolled.
// ============================================================================
__global__ __launch_bounds__(512) void pool_kernel(float* __restrict__ out) {
    const int gz = blockIdx.z;
    const int g  = gz / GF;
    const int f  = gz - g * GF;
    const int b  = blockIdx.y;
    const int p0 = blockIdx.x * PT;

    const int ps  = d_ps[g];
    const int ws  = d_ws[g];
    const int L   = d_L[g];
    const int wsh = ws >> 1;

    extern __shared__ float sm[];
    float* es   = sm + ES_OFF;     // staged energy span
    float* wins = sm + WIN_OFF;    // [ws]
    float* part = sm + PART_OFF;   // [PSUB][PT]

    const int tid = threadIdx.x;
    const int jstart = p0 * ps - wsh;
    const int span   = (PT - 1) * ps + ws;

    const float* ef = d_energy + d_ebase[g] + (f * NBATCH + b) * L;
    for (int i = tid; i < span; i += 512) {
        const int j = jstart + i;
        es[i] = ((unsigned)j < (unsigned)L) ? __ldg(ef + j) : 0.f;
    }
    for (int i = tid; i < ws; i += 512)
        wins[i] = d_win[g][f][i];
    __syncthreads();

    const int pl  = tid & (PT - 1);
    const int sub = tid >> 6;

    const int ws8   = (ws + PSUB - 1) / PSUB;
    const int wbase = sub * ws8;
    int wlen = ws - wbase;
    if (wlen > ws8) wlen = ws8;

    float a0 = 0.f, a1 = 0.f;
    if (wlen > 0) {
        const float* ep = es + pl * ps;
        const int off   = pl % wlen;
        const int wmid  = wbase + off;       // skewed start
        const int wend  = wbase + wlen;
        // Segment 1: [wmid, wend)
        int w = wmid;
        #pragma unroll 4
        for (; w + 1 < wend; w += 2) {
            a0 = fmaf(wins[w],     ep[w],     a0);
            a1 = fmaf(wins[w + 1], ep[w + 1], a1);
        }
        if (w < wend) a0 = fmaf(wins[w], ep[w], a0);
        // Segment 2: [wbase, wmid)
        w = wbase;
        #pragma unroll 4
        for (; w + 1 < wmid; w += 2) {
            a0 = fmaf(wins[w],     ep[w],     a0);
            a1 = fmaf(wins[w + 1], ep[w + 1], a1);
        }
        if (w < wmid) a0 = fmaf(wins[w], ep[w], a0);
    }
    part[sub * PT + pl] = a0 + a1;
    __syncthreads();

    if (tid < PT) {
        float s = 0.f;
        #pragma unroll
        for (int k2 = 0; k2 < PSUB; k2++)
            s += part[k2 * PT + tid];
        const int p = p0 + tid;
        if (p < NP)
            out[(b * NP + p) * NF + g * GF + f] = s;
    }
}

// ============================================================================
extern "C" void kernel_launch(void* const* d_in, const int* in_sizes, int n_in,
                              void* d_out, int out_size) {
    const float* x  = (const float*)d_in[0];  // (32, 64000, 1) f32
    const float* cf = (const float*)d_in[1];  // (40,) f32
    const float* bw = (const float*)d_in[2];  // (40,) f32
    const float* pw = (const float*)d_in[3];  // (40,) f32
    float* out = (float*)d_out;               // (32, 400, 40) f32

    cudaFuncSetAttribute(conv_kernel, cudaFuncAttributeMaxDynamicSharedMemorySize, CONV_SMEM);
    cudaFuncSetAttribute(pool_kernel, cudaFuncAttributeMaxDynamicSharedMemorySize, POOL_SMEM);

    setup_meta<<<1, 32>>>(cf, bw);
    setup_weights<<<dim3(8, NG), 256>>>(cf, bw, pw);

    conv_kernel<<<dim3(125, NBATCH, NG), 256, CONV_SMEM>>>(x);

    // Pool: ceil(400/64) = 7 p-tiles, 40 (g,f) planes.
    pool_kernel<<<dim3((NP + PT - 1) / PT, NBATCH, NG * GF), 512, POOL_SMEM>>>(out);
}

// round 17
// speedup vs baseline: 1.2458x; 1.2458x over previous
#include <cuda_runtime.h>
#include <math.h>

#define NF     40
#define NG     4
#define GF     10
#define TT     64000
#define NBATCH 32
#define NP     400
#define WSMAX  404
#define POSB   512          // positions per pass-1 block (256 threads x 2)
#define WGTCAP 8192         // per-group weight floats (cs*qm*20 + 12)
#define CONV_SMEM 43008
#define PT     64           // pool outputs per block
#define PSUB   8            // w-segments per output (ps divisible by 8 for all groups)
// pool smem float offsets (padded-sigma layout: 66*(ps+1) <= 66*161 = 10626)
#define ES_OFF   0
#define WIN_OFF  10640
#define PART_OFF 11056      // WIN region 416 >= ws(401)
#define POOL_SMEM 46272     // (11056 + 512) * 4 bytes

// ---- per-launch-computed meta + tables + scratch (zero-init .bss) ----
__device__ int   d_cs[NG], d_ps[NG], d_k[NG], d_qn[NG], d_qm[NG], d_ws[NG], d_L[NG];
__device__ int   d_ebase[NG];
__device__ float d_wgt[NG][WGTCAP];           // [r][q][f*2+{cos,sin}] pairs + center norms
__device__ float d_win[NG][GF][WSMAX];
__device__ float d_energy[81920000];          // [g]{[f][b][j]} planes

// ============================================================================
// Setup 1: meta. One tiny block.
// ============================================================================
__global__ void setup_meta(const float* __restrict__ cf,
                           const float* __restrict__ bw) {
    const int tid = threadIdx.x;
    const double Zd  = sqrt(2.0 * log(2.0)) / M_PI;
    const float bwlo = (float)(2.0   * Zd);
    const float bwhi = (float)(401.0 * Zd);
    const float pi_f = (float)M_PI;

    if (tid < NG) {
        const int g = tid;
        float cfm = 0.f, bwm = 0.f;
        for (int f = 0; f < GF; f++) {
            float c = fminf(fmaxf(cf[g * GF + f], 0.f), pi_f);
            float b = fminf(fmaxf(bw[g * GF + f], bwlo), bwhi);
            cfm = fmaxf(cfm, c);
            bwm = fmaxf(bwm, b);
        }
        double s = M_PI / (double)cfm;
        if (s < 1.0) s = 1.0;
        const int divs[12] = {160, 80, 40, 32, 20, 16, 10, 8, 5, 4, 2, 1};
        int cs = 1;
        for (int i = 0; i < 12; i++)
            if ((double)divs[i] <= s) { cs = divs[i]; break; }
        int k = (int)((double)bwm * 3.0);
        if ((k & 1) == 0) k += 1;
        int ws = (int)(401.0 / (double)cs + 0.5);
        if ((ws & 1) == 0) ws += 1;

        const int kh = k >> 1;
        d_cs[g] = cs;
        d_ps[g] = 160 / cs;
        d_k[g]  = k;
        d_qn[g] = (k + cs - 1) / cs;
        d_qm[g] = kh / cs + 1;        // pair-slot count per residue
        d_ws[g] = ws;
        d_L[g]  = (TT - 1) / cs + 1;
    }
    __syncthreads();
    if (tid == 0) {
        int acc = 0;
        for (int g = 0; g < NG; g++) {
            d_ebase[g] = acc;
            acc += NBATCH * d_L[g] * GF;
        }
    }
}

// ============================================================================
// Setup 2: symmetric-pair Gabor weights + pooling windows. grid (8, NG) x 256.
// ============================================================================
__global__ void setup_weights(const float* __restrict__ cf,
                              const float* __restrict__ bw,
                              const float* __restrict__ pw) {
    const int g   = blockIdx.y;
    const int cs  = d_cs[g];
    const int qmA = d_qm[g];
    const int k   = d_k[g];
    const int ws  = d_ws[g];
    const int kh  = k >> 1;

    const double Zd  = sqrt(2.0 * log(2.0)) / M_PI;
    const float bwlo = (float)(2.0   * Zd);
    const float bwhi = (float)(401.0 * Zd);
    const float pi_f = (float)M_PI;

    const int stride = gridDim.x * blockDim.x;
    const int t0 = blockIdx.x * blockDim.x + threadIdx.x;

    const int wtot = cs * qmA * 20;
    for (int i = t0; i < wtot; i += stride) {
        const int qr  = i / 20;
        const int f2  = i - qr * 20;
        const int f   = f2 >> 1;
        const int sel = f2 & 1;
        const int r   = qr / qmA;
        const int q   = qr - r * qmA;
        const int t   = q * cs + r;
        float v = 0.f;
        if (t >= 1 && t <= kh) {
            const int gi = g * GF + f;
            const float cfc = fminf(fmaxf(cf[gi], 0.f), pi_f);
            const float bwc = fminf(fmaxf(bw[gi], bwlo), bwhi);
            const double td = (double)t;
            const double bd = (double)bwc;
            const double gauss = exp(-(td * td) / (2.0 * bd * bd));
            const double norm  = 1.0 / (sqrt(2.0 * M_PI) * bd);
            double sn, csn;
            sincos(td * (double)cfc, &sn, &csn);
            v = (float)(norm * (sel ? sn : csn) * gauss);
        }
        d_wgt[g][i] = v;
    }
    // center norms
    for (int i = t0; i < GF; i += stride) {
        const int gi = g * GF + i;
        const float bwc = fminf(fmaxf(bw[gi], bwlo), bwhi);
        d_wgt[g][wtot + i] = (float)(1.0 / (sqrt(2.0 * M_PI) * (double)bwc));
    }
    if (t0 < 2) d_wgt[g][wtot + GF + t0] = 0.f;   // pad for float4 reads

    // pooling windows
    for (int i = t0; i < GF * ws; i += stride) {
        const int f = i / ws;
        const int w = i - f * ws;
        const int gi = g * GF + f;
        const float pwc = fminf(fmaxf(pw[gi], (float)(2.0 / 401.0)), 0.5f);
        const double sigma = (double)pwc / (double)cs * 401.0 / (double)ws;
        const double c = 0.5 * (double)(ws - 1);
        const double u = ((double)w - c) / (sigma * c);
        d_win[g][f][w] = (float)exp(-0.5 * u * u);
    }
}

// ============================================================================
// Pass 1: symmetric Gabor conv energy (scalar FFMA — measured ~181 us).
// ============================================================================
__global__ __launch_bounds__(256) void conv_kernel(const float* __restrict__ x) {
    const int g = blockIdx.z;
    const int b = blockIdx.y;

    const int cs  = d_cs[g];
    const int qn  = d_qn[g];
    const int qmA = d_qm[g];
    const int L   = d_L[g];
    const int kh  = d_k[g] >> 1;

    const int j0 = blockIdx.x * POSB;
    if (j0 >= L) return;

    const int mlen  = POSB / 2 + 256 + qn;
    const int mlenP = mlen | 1;

    extern __shared__ float sm[];
    float* xr = sm;                                     // [cs][mlenP]
    const int wofs = ((cs * mlenP) + 3) & ~3;
    float* wsm = sm + wofs;                             // pairs + center

    const int tid  = threadIdx.x;
    const int gofs = j0 * cs - kh;
    const float* xb = x + b * TT;

    const int xtot = cs * mlen;
    for (int i = tid; i < xtot; i += 256) {
        const int gi = gofs + i;
        const float v = ((unsigned)gi < (unsigned)TT) ? xb[gi] : 0.f;
        const int r = i % cs;
        const int m = i / cs;
        xr[r * mlenP + m] = v;
    }
    const int wtot = cs * qmA * 20 + 12;
    for (int i = tid; i < wtot; i += 256)
        wsm[i] = d_wgt[g][i];
    __syncthreads();

    float C0[GF], S0[GF], C1[GF], S1[GF];
    #pragma unroll
    for (int f = 0; f < GF; f++) { C0[f] = S0[f] = C1[f] = S1[f] = 0.f; }

    // Center tap (t = 0): contributes only to C (sin(0)=0).
    {
        const float* rowC = xr + (kh % cs) * mlenP + (kh / cs) + tid;
        const float xc0 = rowC[0];
        const float xc1 = rowC[256];
        const float4* c4 = reinterpret_cast<const float4*>(wsm + cs * qmA * 20);
        const float4 n0 = c4[0], n1 = c4[1], n2 = c4[2];
        C0[0] = fmaf(n0.x, xc0, C0[0]); C1[0] = fmaf(n0.x, xc1, C1[0]);
        C0[1] = fmaf(n0.y, xc0, C0[1]); C1[1] = fmaf(n0.y, xc1, C1[1]);
        C0[2] = fmaf(n0.z, xc0, C0[2]); C1[2] = fmaf(n0.z, xc1, C1[2]);
        C0[3] = fmaf(n0.w, xc0, C0[3]); C1[3] = fmaf(n0.w, xc1, C1[3]);
        C0[4] = fmaf(n1.x, xc0, C0[4]); C1[4] = fmaf(n1.x, xc1, C1[4]);
        C0[5] = fmaf(n1.y, xc0, C0[5]); C1[5] = fmaf(n1.y, xc1, C1[5]);
        C0[6] = fmaf(n1.z, xc0, C0[6]); C1[6] = fmaf(n1.z, xc1, C1[6]);
        C0[7] = fmaf(n1.w, xc0, C0[7]); C1[7] = fmaf(n1.w, xc1, C1[7]);
        C0[8] = fmaf(n2.x, xc0, C0[8]); C1[8] = fmaf(n2.x, xc1, C1[8]);
        C0[9] = fmaf(n2.y, xc0, C0[9]); C1[9] = fmaf(n2.y, xc1, C1[9]);
    }

    // Tap pairs t = q*cs + r, t in [1, kh].
    #pragma unroll 1
    for (int r = 0; r < cs; r++) {
        const int qlo = (r == 0) ? 1 : 0;
        const int aM  = (kh - r) / cs;
        const int sM  = (kh - r) % cs;
        const int bP  = (kh + r) / cs;
        const int sP  = (kh + r) % cs;
        const float* rowP = xr + sP * mlenP + tid + bP;
        const float* rowM = xr + sM * mlenP + tid + aM;
        const float* wr = wsm + r * qmA * 20;
        #pragma unroll 1
        for (int q = qlo; q <= aM; q++) {
            const float xp0 = rowP[q];
            const float xm0 = rowM[-q];
            const float xp1 = rowP[256 + q];
            const float xm1 = rowM[256 - q];
            const float u0 = xp0 + xm0, dd0 = xp0 - xm0;
            const float u1 = xp1 + xm1, dd1 = xp1 - xm1;
            const float4* w4 = reinterpret_cast<const float4*>(wr + q * 20);
            #pragma unroll
            for (int c = 0; c < 5; c++) {
                const float4 w = w4[c];
                const int f0 = 2 * c, f1 = 2 * c + 1;
                C0[f0] = fmaf(w.x, u0,  C0[f0]);
                S0[f0] = fmaf(w.y, dd0, S0[f0]);
                C0[f1] = fmaf(w.z, u0,  C0[f1]);
                S0[f1] = fmaf(w.w, dd0, S0[f1]);
                C1[f0] = fmaf(w.x, u1,  C1[f0]);
                S1[f0] = fmaf(w.y, dd1, S1[f0]);
                C1[f1] = fmaf(w.z, u1,  C1[f1]);
                S1[f1] = fmaf(w.w, dd1, S1[f1]);
            }
        }
    }

    // Plane stores: e[f][b][j] — coalesced per filter.
    float* eg = d_energy + d_ebase[g];
    const int ja = j0 + tid;
    const int jb = j0 + 256 + tid;
    #pragma unroll
    for (int f = 0; f < GF; f++) {
        float* pf = eg + (f * NBATCH + b) * L;
        if (ja < L) pf[ja] = fmaf(C0[f], C0[f], S0[f] * S0[f]);
        if (jb < L) pf[jb] = fmaf(C1[f], C1[f], S1[f] * S1[f]);
    }
}

// ============================================================================
// Pass 2: pooling with PADDED-SIGMA smem layout.
// Element j = m*ps + rr stored at es[m*(ps+1) + rr]. Thread pl reading
// w = t*ps + wi hits (pl+t)*(ps+1) + wi: lane stride ps+1 is ODD ->
// conflict-free, inner loop over wi is LINEAR with warp-UNIFORM bounds.
// Block = (p-tile of 64, b, g*f). 512 threads = 64 outputs x 8 sub-ranges
// of [0, ps) per window-block t (ps divisible by 8 for all groups).
// ============================================================================
__global__ __launch_bounds__(512) void pool_kernel(float* __restrict__ out) {
    const int gz = blockIdx.z;
    const int g  = gz / GF;
    const int f  = gz - g * GF;
    const int b  = blockIdx.y;
    const int p0 = blockIdx.x * PT;

    const int ps  = d_ps[g];
    const int ws  = d_ws[g];
    const int L   = d_L[g];
    const int wsh = ws >> 1;
    const int ps1 = ps + 1;

    extern __shared__ float sm[];
    float* es   = sm + ES_OFF;     // sigma-padded energy span
    float* wins = sm + WIN_OFF;    // [ws]
    float* part = sm + PART_OFF;   // [PSUB][PT]

    const int tid = threadIdx.x;
    const int jstart = p0 * ps - wsh;
    const int span   = (PT - 1) * ps + ws;

    // Stage energy with sigma layout; maintain (m, rr) incrementally.
    {
        const float* ef = d_energy + d_ebase[g] + (f * NBATCH + b) * L;
        const int stepm = 512 / ps;          // exact quotient parts
        const int stepr = 512 - stepm * ps;
        int m  = tid / ps;
        int rr = tid - m * ps;
        for (int i = tid; i < span; i += 512) {
            const int j = jstart + i;
            es[m * ps1 + rr] = ((unsigned)j < (unsigned)L) ? __ldg(ef + j) : 0.f;
            m += stepm;
            rr += stepr;
            if (rr >= ps) { rr -= ps; m++; }
        }
    }
    for (int i = tid; i < ws; i += 512)
        wins[i] = d_win[g][f][i];
    __syncthreads();

    const int pl  = tid & (PT - 1);
    const int sub = tid >> 6;              // warp-uniform
    const int pss = ps >> 3;               // ps/8, exact

    const int wlo = sub * pss;
    const float* epb = es + pl * ps1;

    float acc = 0.f;
    // Window blocks t: w = t*ps + wi. nblk = ceil(ws/ps) (= 3 for all groups).
    #pragma unroll 1
    for (int t = 0; t * ps < ws; t++) {
        const int wrem = ws - t * ps;                    // elements in this block
        int whi = wlo + pss;
        if (whi > wrem) whi = wrem;                      // last (partial) block
        const float* ep = epb + t * ps1;
        const float* wp = wins + t * ps;
        #pragma unroll 4
        for (int wi = wlo; wi < whi; wi++)
            acc = fmaf(wp[wi], ep[wi], acc);
    }

    part[sub * PT + pl] = acc;
    __syncthreads();

    if (tid < PT) {
        float s = 0.f;
        #pragma unroll
        for (int k2 = 0; k2 < PSUB; k2++)
            s += part[k2 * PT + tid];
        const int p = p0 + tid;
        if (p < NP)
            out[(b * NP + p) * NF + g * GF + f] = s;
    }
}

// ============================================================================
extern "C" void kernel_launch(void* const* d_in, const int* in_sizes, int n_in,
                              void* d_out, int out_size) {
    const float* x  = (const float*)d_in[0];  // (32, 64000, 1) f32
    const float* cf = (const float*)d_in[1];  // (40,) f32
    const float* bw = (const float*)d_in[2];  // (40,) f32
    const float* pw = (const float*)d_in[3];  // (40,) f32
    float* out = (float*)d_out;               // (32, 400, 40) f32

    cudaFuncSetAttribute(conv_kernel, cudaFuncAttributeMaxDynamicSharedMemorySize, CONV_SMEM);
    cudaFuncSetAttribute(pool_kernel, cudaFuncAttributeMaxDynamicSharedMemorySize, POOL_SMEM);

    setup_meta<<<1, 32>>>(cf, bw);
    setup_weights<<<dim3(8, NG), 256>>>(cf, bw, pw);

    conv_kernel<<<dim3(125, NBATCH, NG), 256, CONV_SMEM>>>(x);

    // Pool: ceil(400/64) = 7 p-tiles, 40 (g,f) planes.
    pool_kernel<<<dim3((NP + PT - 1) / PT, NBATCH, NG * GF), 512, POOL_SMEM>>>(out);
}